// round 6
// baseline (speedup 1.0000x reference)
#include <cuda_runtime.h>

// Problem constants
#define N_ROWS   1344              // B*C = 64*21
#define R_WIN    32                // windows per row (L/MAX_PL = 1024/32)
#define DM       512               // D_MODEL
#define TGT      4                 // MAX_PL/MIN_PL
#define PE_LEN   128               // R_WIN * TGT
#define MAIN_OUT ((long long)N_ROWS * PE_LEN * DM)  // 88080384
#define EMB_BLOCKS (N_ROWS * 2)    // 2688

// ---------------------------------------------------------------------------
// Single fused kernel. Block b < 2688: n = b>>1, dims [(b&1)*256, +256).
//   phase 1: cooperative x-row load into smem
//   phase 2: in-block classifier (thread = (window tid>>3, h-octet tid&7),
//            shfl_xor over 8 lanes) -> s_pred[32]. Scoped so its temporaries
//            die before the weight cache is loaded.
//   phase 3: R3's proven main loop: ALL weights in registers (56 floats),
//            xv[8] preloaded per window, PE rotation recurrence, 4 stores.
// NO __launch_bounds__ min-blocks: R4/R5 proved capping regs to 80 makes
// ptxas spill to local, tripling L1 traffic (94% L1, 2.7x slowdown).
// ---------------------------------------------------------------------------
__global__ void __launch_bounds__(256)
fused_kernel(const float* __restrict__ x,
             const float* __restrict__ w1,
             const float* __restrict__ b1,
             const float* __restrict__ w2,
             const float* __restrict__ b2,
             const float* __restrict__ we0,   // [512][8]
             const float* __restrict__ we1,   // [512][16]
             const float* __restrict__ we2,   // [512][32]
             float* __restrict__ out,
             long long tail_start, long long total) {
    if (blockIdx.x >= EMB_BLOCKS) {
        long long i = tail_start + (long long)(blockIdx.x - EMB_BLOCKS) * 256 + threadIdx.x;
        if (i < total) out[i] = 21.0f;
        return;
    }

    __shared__ __align__(16) float s_x[R_WIN * 32];   // 4 KB
    __shared__ unsigned char s_pred[R_WIN];

    const int tid  = threadIdx.x;
    const int n    = blockIdx.x >> 1;
    const int dblk = (blockIdx.x & 1) << 8;
    const int d    = dblk + tid;

    // --- phase 1: stage x row ---
    ((float4*)s_x)[tid] = ((const float4*)(x + (size_t)n * 1024))[tid];
    __syncthreads();

    // --- phase 2: classifier (scoped; redundant across the two d-halves) ---
    {
        int w = tid >> 3;       // window 0..31
        int p = tid & 7;        // h-octet 0..7
        const float4* xw = (const float4*)(s_x + w * 32);
        float4 xv[8];
#pragma unroll
        for (int i = 0; i < 8; i++) xv[i] = xw[i];

        float l0 = 0.f, l1 = 0.f, l2 = 0.f;
#pragma unroll
        for (int j = 0; j < 8; j++) {
            int h = p * 8 + j;
            const float4* wr = (const float4*)(w1 + h * 32);
            float a0 = 0.f, a1 = 0.f, a2 = 0.f, a3 = 0.f;
#pragma unroll
            for (int i = 0; i < 8; i++) {
                float4 wv = __ldg(&wr[i]);
                a0 = fmaf(wv.x, xv[i].x, a0);
                a1 = fmaf(wv.y, xv[i].y, a1);
                a2 = fmaf(wv.z, xv[i].z, a2);
                a3 = fmaf(wv.w, xv[i].w, a3);
            }
            float hv = b1[h] + ((a0 + a1) + (a2 + a3));
            hv = fmaxf(hv, 0.0f);
            l0 = fmaf(w2[h], hv, l0);
            l1 = fmaf(w2[64 + h], hv, l1);
            l2 = fmaf(w2[128 + h], hv, l2);
        }
#pragma unroll
        for (int m = 1; m < 8; m <<= 1) {
            l0 += __shfl_xor_sync(0xffffffffu, l0, m);
            l1 += __shfl_xor_sync(0xffffffffu, l1, m);
            l2 += __shfl_xor_sync(0xffffffffu, l2, m);
        }
        if (p == 0) {
            l0 += b2[0]; l1 += b2[1]; l2 += b2[2];
            int pr = 0;
            float mm = l0;
            if (l1 > mm) { mm = l1; pr = 1; }   // strict > = first-max (jnp.argmax)
            if (l2 > mm) { mm = l2; pr = 2; }
            s_pred[w] = (unsigned char)pr;
        }
    }
    __syncthreads();

    // --- phase 3: R3's main loop, weights in registers ---
    float4 r0[2], r1[4], r2[8];
    {
        const float4* p0 = (const float4*)(we0 + d * 8);
        r0[0] = p0[0]; r0[1] = p0[1];
        const float4* p1 = (const float4*)(we1 + d * 16);
#pragma unroll
        for (int i = 0; i < 4; i++) r1[i] = p1[i];
        const float4* p2 = (const float4*)(we2 + d * 32);
#pragma unroll
        for (int i = 0; i < 8; i++) r2[i] = p2[i];
    }

    // PE rotation recurrence setup.
    const float kLn = -9.21034037197618f / (float)DM;   // -ln(10000)/512
    float delta = expf((float)(d & ~1) * kLn);
    float sd, cd;
    sincosf(delta, &sd, &cd);
    float s = 0.0f, c = 1.0f;
    const bool use_cos = (d & 1);

    float* outn = out + (size_t)n * (PE_LEN * DM);

#pragma unroll 1
    for (int w = 0; w < R_WIN; w++) {
        int pred = s_pred[w];

        const float4* xq = (const float4*)(s_x + w * 32);
        float4 xv[8];
#pragma unroll
        for (int i = 0; i < 8; i++) xv[i] = xq[i];

        float v0, v1, v2, v3;
        if (pred == 0) {
            // 4 patches of 8; repeat idx = [0,1,2,3]
            float acc[4];
#pragma unroll
            for (int k = 0; k < 4; k++) {
                float t = r0[0].x * xv[k*2].x;
                t = fmaf(r0[0].y, xv[k*2].y, t);
                t = fmaf(r0[0].z, xv[k*2].z, t);
                t = fmaf(r0[0].w, xv[k*2].w, t);
                t = fmaf(r0[1].x, xv[k*2+1].x, t);
                t = fmaf(r0[1].y, xv[k*2+1].y, t);
                t = fmaf(r0[1].z, xv[k*2+1].z, t);
                t = fmaf(r0[1].w, xv[k*2+1].w, t);
                acc[k] = t;
            }
            v0 = acc[0]; v1 = acc[1]; v2 = acc[2]; v3 = acc[3];
        } else if (pred == 1) {
            // 2 patches of 16; repeat idx = [0,0,0,1]
            float a = 0.f, b = 0.f;
#pragma unroll
            for (int i = 0; i < 4; i++) {
                a = fmaf(r1[i].x, xv[i].x, a);
                a = fmaf(r1[i].y, xv[i].y, a);
                a = fmaf(r1[i].z, xv[i].z, a);
                a = fmaf(r1[i].w, xv[i].w, a);
            }
#pragma unroll
            for (int i = 0; i < 4; i++) {
                b = fmaf(r1[i].x, xv[4 + i].x, b);
                b = fmaf(r1[i].y, xv[4 + i].y, b);
                b = fmaf(r1[i].z, xv[4 + i].z, b);
                b = fmaf(r1[i].w, xv[4 + i].w, b);
            }
            v0 = a; v1 = a; v2 = a; v3 = b;
        } else {
            // 1 patch of 32 -> replicated 4x
            float c0 = 0.f, c1 = 0.f, c2 = 0.f, c3 = 0.f;
#pragma unroll
            for (int i = 0; i < 8; i += 4) {
                c0 = fmaf(r2[i].x,   xv[i].x,   c0);
                c0 = fmaf(r2[i].y,   xv[i].y,   c0);
                c0 = fmaf(r2[i].z,   xv[i].z,   c0);
                c0 = fmaf(r2[i].w,   xv[i].w,   c0);
                c1 = fmaf(r2[i+1].x, xv[i+1].x, c1);
                c1 = fmaf(r2[i+1].y, xv[i+1].y, c1);
                c1 = fmaf(r2[i+1].z, xv[i+1].z, c1);
                c1 = fmaf(r2[i+1].w, xv[i+1].w, c1);
                c2 = fmaf(r2[i+2].x, xv[i+2].x, c2);
                c2 = fmaf(r2[i+2].y, xv[i+2].y, c2);
                c2 = fmaf(r2[i+2].z, xv[i+2].z, c2);
                c2 = fmaf(r2[i+2].w, xv[i+2].w, c2);
                c3 = fmaf(r2[i+3].x, xv[i+3].x, c3);
                c3 = fmaf(r2[i+3].y, xv[i+3].y, c3);
                c3 = fmaf(r2[i+3].z, xv[i+3].z, c3);
                c3 = fmaf(r2[i+3].w, xv[i+3].w, c3);
            }
            float cc = (c0 + c1) + (c2 + c3);
            v0 = cc; v1 = cc; v2 = cc; v3 = cc;
        }

        // PE via rotation recurrence — 4 positions, zero loads.
        float p0 = use_cos ? c : s;
        { float ns = fmaf(s, cd, c * sd); float nc = fmaf(c, cd, -s * sd); s = ns; c = nc; }
        float p1 = use_cos ? c : s;
        { float ns = fmaf(s, cd, c * sd); float nc = fmaf(c, cd, -s * sd); s = ns; c = nc; }
        float p2 = use_cos ? c : s;
        { float ns = fmaf(s, cd, c * sd); float nc = fmaf(c, cd, -s * sd); s = ns; c = nc; }
        float p3 = use_cos ? c : s;
        { float ns = fmaf(s, cd, c * sd); float nc = fmaf(c, cd, -s * sd); s = ns; c = nc; }

        float* o = outn + (size_t)w * (TGT * DM) + d;
        o[0 * DM] = v0 + p0;
        o[1 * DM] = v1 + p1;
        o[2 * DM] = v2 + p2;
        o[3 * DM] = v3 + p3;
    }
}

extern "C" void kernel_launch(void* const* d_in, const int* in_sizes, int n_in,
                              void* d_out, int out_size) {
    const float* x   = (const float*)d_in[0];
    const float* w1  = (const float*)d_in[1];
    const float* b1  = (const float*)d_in[2];
    const float* w2  = (const float*)d_in[3];
    const float* b2  = (const float*)d_in[4];
    const float* we0 = (const float*)d_in[5];
    const float* we1 = (const float*)d_in[6];
    const float* we2 = (const float*)d_in[7];
    float* out = (float*)d_out;

    long long total = (long long)out_size;
    long long tail  = (total > MAIN_OUT) ? (total - MAIN_OUT) : 0;
    int tail_blocks = (int)((tail + 255) / 256);

    fused_kernel<<<EMB_BLOCKS + tail_blocks, 256>>>(
        x, w1, b1, w2, b2, we0, we1, we2, out, MAIN_OUT, total);
}

// round 7
// speedup vs baseline: 2.1869x; 2.1869x over previous
#include <cuda_runtime.h>

// Problem constants
#define N_ROWS   1344              // B*C = 64*21
#define R_WIN    32                // windows per row (L/MAX_PL = 1024/32)
#define NWIN     (N_ROWS * R_WIN)  // 43008
#define DM       512               // D_MODEL
#define TGT      4                 // MAX_PL/MIN_PL
#define PE_LEN   128               // R_WIN * TGT
#define MAIN_OUT ((long long)N_ROWS * PE_LEN * DM)  // 88080384
#define CLS_BLOCKS ((NWIN + 255) / 256)             // 168

typedef unsigned long long u64;

// f32x2 packed helpers (sm_103a FFMA2 — PTX-only form).
__device__ __forceinline__ u64 fma2(u64 a, u64 b, u64 c) {
    u64 d; asm("fma.rn.f32x2 %0, %1, %2, %3;" : "=l"(d) : "l"(a), "l"(b), "l"(c));
    return d;
}
__device__ __forceinline__ u64 mul2(u64 a, u64 b) {
    u64 d; asm("mul.rn.f32x2 %0, %1, %2;" : "=l"(d) : "l"(a), "l"(b));
    return d;
}
__device__ __forceinline__ u64 add2(u64 a, u64 b) {
    u64 d; asm("add.rn.f32x2 %0, %1, %2;" : "=l"(d) : "l"(a), "l"(b));
    return d;
}
__device__ __forceinline__ float hadd2(u64 a) {
    float lo, hi;
    asm("mov.b64 {%0, %1}, %2;" : "=f"(lo), "=f"(hi) : "l"(a));
    return lo + hi;
}

// Scratch (no allocation allowed in kernel_launch)
__device__ unsigned char g_pred[NWIN];

// ---------------------------------------------------------------------------
// Kernel 1: classifier + tail fill (R3's proven pre_kernel).
// ---------------------------------------------------------------------------
__global__ void __launch_bounds__(256)
pre_kernel(const float* __restrict__ x,
           const float* __restrict__ w1,
           const float* __restrict__ b1,
           const float* __restrict__ w2,
           const float* __restrict__ b2,
           float* __restrict__ out,
           long long tail_start, long long total) {
    int bid = blockIdx.x;
    if (bid >= CLS_BLOCKS) {
        long long i = tail_start + (long long)(bid - CLS_BLOCKS) * 256 + threadIdx.x;
        if (i < total) out[i] = 21.0f;   // reference returns (x_patch, C=21)
        return;
    }

    int w = bid * blockDim.x + threadIdx.x;
    if (w >= NWIN) return;

    const float4* xw = (const float4*)(x + (size_t)w * 32);
    float4 xv[8];
#pragma unroll
    for (int i = 0; i < 8; i++) xv[i] = xw[i];

    float l0 = b2[0], l1 = b2[1], l2 = b2[2];

#pragma unroll 4
    for (int h = 0; h < 64; h++) {
        const float4* wr = (const float4*)(w1 + h * 32);
        float a0 = 0.f, a1 = 0.f, a2 = 0.f, a3 = 0.f;
#pragma unroll
        for (int i = 0; i < 8; i++) {
            float4 wv = wr[i];
            a0 = fmaf(wv.x, xv[i].x, a0);
            a1 = fmaf(wv.y, xv[i].y, a1);
            a2 = fmaf(wv.z, xv[i].z, a2);
            a3 = fmaf(wv.w, xv[i].w, a3);
        }
        float hv = b1[h] + ((a0 + a1) + (a2 + a3));
        hv = fmaxf(hv, 0.0f);
        l0 = fmaf(w2[h], hv, l0);
        l1 = fmaf(w2[64 + h], hv, l1);
        l2 = fmaf(w2[128 + h], hv, l2);
    }

    int p = 0;
    float m = l0;
    if (l1 > m) { m = l1; p = 1; }   // strict > = first-max (jnp.argmax)
    if (l2 > m) { m = l2; p = 2; }
    g_pred[w] = (unsigned char)p;
}

// ---------------------------------------------------------------------------
// Kernel 2: embedding + repeat + PE + store (R3 mapping, f32x2 packed dots).
// 256 threads/block, two blocks per n: d = (blockIdx&1)*256 + tid.
// Weights live in registers as u64 PAIRS (we0: 4, we1: 8, we2: 16 u64).
// __launch_bounds__(256,2): cap 128 regs == guaranteed 2 CTAs/SM, natural
// usage ~100 so no spill (R4/R5 lesson: the 3-CTA cap at 80 regs spills).
// ---------------------------------------------------------------------------
__global__ void __launch_bounds__(256, 2)
emb_kernel(const float* __restrict__ x,
           const float* __restrict__ we0,   // [512][8]
           const float* __restrict__ we1,   // [512][16]
           const float* __restrict__ we2,   // [512][32]
           float* __restrict__ out) {
    __shared__ __align__(16) float s_x[R_WIN * 32];   // 4 KB
    __shared__ unsigned char s_pred[R_WIN];

    const int tid  = threadIdx.x;
    const int n    = blockIdx.x >> 1;
    const int dblk = (blockIdx.x & 1) << 8;
    const int d    = dblk + tid;

    // Weight cache as packed pairs.
    u64 w0r[4], w1r[8], w2r[16];
    {
        const ulonglong2* p0 = (const ulonglong2*)(we0 + d * 8);
#pragma unroll
        for (int i = 0; i < 2; i++) { ulonglong2 v = p0[i]; w0r[2*i] = v.x; w0r[2*i+1] = v.y; }
        const ulonglong2* p1 = (const ulonglong2*)(we1 + d * 16);
#pragma unroll
        for (int i = 0; i < 4; i++) { ulonglong2 v = p1[i]; w1r[2*i] = v.x; w1r[2*i+1] = v.y; }
        const ulonglong2* p2 = (const ulonglong2*)(we2 + d * 32);
#pragma unroll
        for (int i = 0; i < 8; i++) { ulonglong2 v = p2[i]; w2r[2*i] = v.x; w2r[2*i+1] = v.y; }
    }

    // Cooperative loads: x row (1024 floats = 256 float4) + 32 preds.
    {
        const float4* xg = (const float4*)(x + (size_t)n * 1024);
        ((float4*)s_x)[tid] = xg[tid];
        if (tid < R_WIN) s_pred[tid] = g_pred[n * R_WIN + tid];
    }

    // PE rotation recurrence setup.
    const float kLn = -9.21034037197618f / (float)DM;   // -ln(10000)/512
    float delta = expf((float)(d & ~1) * kLn);
    float sd, cd;
    sincosf(delta, &sd, &cd);
    float s = 0.0f, c = 1.0f;
    const bool use_cos = (d & 1);

    __syncthreads();

    float* outn = out + (size_t)n * (PE_LEN * DM);

#pragma unroll 1
    for (int w = 0; w < R_WIN; w++) {
        int pred = s_pred[w];

        const ulonglong2* xq2 = (const ulonglong2*)(s_x + w * 32);
        u64 xv[16];
#pragma unroll
        for (int i = 0; i < 8; i++) { ulonglong2 v = xq2[i]; xv[2*i] = v.x; xv[2*i+1] = v.y; }

        float v0, v1, v2, v3;
        if (pred == 0) {
            // 4 patches of 8 floats (= 4 u64 each); repeat idx = [0,1,2,3]
            float acc[4];
#pragma unroll
            for (int k = 0; k < 4; k++) {
                u64 a = mul2(w0r[0], xv[4*k]);
                a = fma2(w0r[1], xv[4*k+1], a);
                a = fma2(w0r[2], xv[4*k+2], a);
                a = fma2(w0r[3], xv[4*k+3], a);
                acc[k] = hadd2(a);
            }
            v0 = acc[0]; v1 = acc[1]; v2 = acc[2]; v3 = acc[3];
        } else if (pred == 1) {
            // 2 patches of 16 floats (= 8 u64 each); repeat idx = [0,0,0,1]
            u64 a0 = mul2(w1r[0], xv[0]);
            u64 a1 = mul2(w1r[1], xv[1]);
            a0 = fma2(w1r[2], xv[2], a0);
            a1 = fma2(w1r[3], xv[3], a1);
            a0 = fma2(w1r[4], xv[4], a0);
            a1 = fma2(w1r[5], xv[5], a1);
            a0 = fma2(w1r[6], xv[6], a0);
            a1 = fma2(w1r[7], xv[7], a1);
            float a = hadd2(add2(a0, a1));

            u64 b0 = mul2(w1r[0], xv[8]);
            u64 b1 = mul2(w1r[1], xv[9]);
            b0 = fma2(w1r[2], xv[10], b0);
            b1 = fma2(w1r[3], xv[11], b1);
            b0 = fma2(w1r[4], xv[12], b0);
            b1 = fma2(w1r[5], xv[13], b1);
            b0 = fma2(w1r[6], xv[14], b0);
            b1 = fma2(w1r[7], xv[15], b1);
            float b = hadd2(add2(b0, b1));
            v0 = a; v1 = a; v2 = a; v3 = b;
        } else {
            // 1 patch of 32 floats (= 16 u64) -> replicated 4x
            u64 a0 = mul2(w2r[0], xv[0]);
            u64 a1 = mul2(w2r[1], xv[1]);
            u64 a2 = mul2(w2r[2], xv[2]);
            u64 a3 = mul2(w2r[3], xv[3]);
#pragma unroll
            for (int i = 4; i < 16; i += 4) {
                a0 = fma2(w2r[i],   xv[i],   a0);
                a1 = fma2(w2r[i+1], xv[i+1], a1);
                a2 = fma2(w2r[i+2], xv[i+2], a2);
                a3 = fma2(w2r[i+3], xv[i+3], a3);
            }
            float cc = hadd2(add2(add2(a0, a1), add2(a2, a3)));
            v0 = cc; v1 = cc; v2 = cc; v3 = cc;
        }

        // PE via rotation recurrence — 4 positions, zero loads.
        float p0 = use_cos ? c : s;
        { float ns = fmaf(s, cd, c * sd); float nc = fmaf(c, cd, -s * sd); s = ns; c = nc; }
        float p1 = use_cos ? c : s;
        { float ns = fmaf(s, cd, c * sd); float nc = fmaf(c, cd, -s * sd); s = ns; c = nc; }
        float p2 = use_cos ? c : s;
        { float ns = fmaf(s, cd, c * sd); float nc = fmaf(c, cd, -s * sd); s = ns; c = nc; }
        float p3 = use_cos ? c : s;
        { float ns = fmaf(s, cd, c * sd); float nc = fmaf(c, cd, -s * sd); s = ns; c = nc; }

        float* o = outn + (size_t)w * (TGT * DM) + d;
        o[0 * DM] = v0 + p0;
        o[1 * DM] = v1 + p1;
        o[2 * DM] = v2 + p2;
        o[3 * DM] = v3 + p3;
    }
}

extern "C" void kernel_launch(void* const* d_in, const int* in_sizes, int n_in,
                              void* d_out, int out_size) {
    const float* x   = (const float*)d_in[0];
    const float* w1  = (const float*)d_in[1];
    const float* b1  = (const float*)d_in[2];
    const float* w2  = (const float*)d_in[3];
    const float* b2  = (const float*)d_in[4];
    const float* we0 = (const float*)d_in[5];
    const float* we1 = (const float*)d_in[6];
    const float* we2 = (const float*)d_in[7];
    float* out = (float*)d_out;

    long long total = (long long)out_size;
    long long tail  = (total > MAIN_OUT) ? (total - MAIN_OUT) : 0;
    int tail_blocks = (int)((tail + 255) / 256);

    pre_kernel<<<CLS_BLOCKS + tail_blocks, 256>>>(x, w1, b1, w2, b2,
                                                  out, MAIN_OUT, total);
    emb_kernel<<<N_ROWS * 2, 256>>>(x, we0, we1, we2, out);
}